// round 3
// baseline (speedup 1.0000x reference)
#include <cuda_runtime.h>

// Problem dims (fixed by the reference)
#define Bn 8
#define Cn 8
#define Hn 512
#define Wn 512
#define HWn (Hn * Wn)

// Global double accumulators: [0] = sum of per-pixel "per-channel" (NC-normalized)
// contributions, [1] = sum of per-pixel "per-pixel" (NP-normalized) contributions.
__device__ double g_acc[2];

__device__ __forceinline__ float ex2f(float x) {
    float r; asm("ex2.approx.f32 %0, %1;" : "=f"(r) : "f"(x)); return r;
}
__device__ __forceinline__ float lg2f(float x) {
    float r; asm("lg2.approx.f32 %0, %1;" : "=f"(r) : "f"(x)); return r;
}

__global__ void zero_acc_kernel() {
    g_acc[0] = 0.0;
    g_acc[1] = 0.0;
}

// Per-channel step for one branch (atts or dets).
//   x = logit at center (channel k), y = logit at neighbor (channel 7-k, offset k)
//   t = con_target[k] (binary)
// Uses:
//   softplus(x) = ln(1+e^x) = s       -> conn BCE term = s - t*x
//   log p = x - s ; log q = y - sy
//   v = p*q ; log v = (x-s)+(y-sy) ; v = exp(log v)
//   log(1-v) = ln(1 + e^x + e^y) - s - sy
// Border (out-of-bounds neighbor): v = 0, clog(v) = -100, log(1-v) = 0.
__device__ __forceinline__ void branch_step(
    const float* __restrict__ p, int cidx, int nidx, bool ib, float t,
    float& conn, float& bic, float& sv, float& mv)
{
    const float L2E = 1.4426950408889634f;
    const float LN2 = 0.6931471805599453f;

    float x = __ldg(p + cidx);
    float u = ex2f(x * L2E);          // e^x
    float s = LN2 * lg2f(1.0f + u);   // softplus(x)
    conn += s - t * x;                // BCE(sigmoid(x), t)

    float v, logv, l1mv;
    if (ib) {
        float y  = __ldg(p + nidx);
        float uy = ex2f(y * L2E);
        float sy = LN2 * lg2f(1.0f + uy);
        logv = (x - s) + (y - sy);
        v    = ex2f(logv * L2E);
        l1mv = LN2 * lg2f(1.0f + u + uy) - s - sy;
    } else {
        v = 0.0f; logv = -100.0f; l1mv = 0.0f;
    }
    sv += v;
    mv = fminf(mv, v);
    // BCE(v, t), binary t, with the -100 log clamp
    bic += (t > 0.5f) ? -fmaxf(logv, -100.0f) : -fmaxf(l1mv, -100.0f);
}

__global__ __launch_bounds__(256) void bicon_main_kernel(
    const float* __restrict__ atts,
    const float* __restrict__ dets,
    const float* __restrict__ target,
    const float* __restrict__ con)
{
    const int w = blockIdx.x * 256 + threadIdx.x;
    const int h = blockIdx.y;
    const int b = blockIdx.z;

    // 8-neighborhood in raster order; vote channel k pairs center channel k
    // with channel (7-k) at offset (DH[k], DW[k]).
    const int DH[8] = {-1, -1, -1,  0, 0,  1, 1, 1};
    const int DW[8] = {-1,  0,  1, -1, 1, -1, 0, 1};
    const float L2E = 1.4426950408889634f;
    const float LN2 = 0.6931471805599453f;

    float csum = 0.0f;
    float conn1 = 0.0f, conn2 = 0.0f;
    float bic1  = 0.0f, bic2  = 0.0f;
    float sv1 = 0.0f, sv2 = 0.0f;
    float mv1 = 1e30f, mv2 = 1e30f;   // mv1 unused, kept for symmetry

    const int base_pix = h * Wn + w;

#pragma unroll
    for (int k = 0; k < 8; k++) {
        const int nh = h + DH[k];
        const int nw = w + DW[k];
        const bool ib = ((unsigned)nh < (unsigned)Hn) && ((unsigned)nw < (unsigned)Wn);
        const int cidx = (b * Cn + k) * HWn + base_pix;
        const int nidx = ((b * Cn + (7 - k)) * Hn + nh) * Wn + nw;

        const float t = __ldg(con + cidx);
        csum += t;

        branch_step(atts, cidx, nidx, ib, t, conn1, bic1, sv1, mv1);
        branch_step(dets, cidx, nidx, ib, t, conn2, bic2, sv2, mv2);
    }

    const float tp = __ldg(target + b * HWn + base_pix);
    const bool tpos = (tp > 0.5f);

    // glo_map BCE (atts branch)
    const float g1  = sv1 * 0.125f;
    const float lg1  = fmaxf(LN2 * lg2f(g1),        -100.0f);
    const float l1g1 = fmaxf(LN2 * lg2f(1.0f - g1), -100.0f);
    const float bce1 = tpos ? -lg1 : -l1g1;

    // decouple BCE (dets branch)
    const float g2 = sv2 * 0.125f;
    const bool edge = (csum > 0.5f) && (csum < 7.5f);
    const float dec = edge ? (1.0f - mv2) : g2;
    const float ld   = fmaxf(LN2 * lg2f(dec),        -100.0f);
    const float l1d  = fmaxf(LN2 * lg2f(1.0f - dec), -100.0f);
    const float de2  = tpos ? -ld : -l1d;

    // Per-thread contributions, normalized at finalize:
    //   cNC / (B*C*H*W),  cNP / (B*H*W)
    float cNC = 0.2f * (bic1 + bic2) + 0.8f * (conn1 + conn2);
    float cNP = bce1 + de2;

    // Warp reduce both
#pragma unroll
    for (int off = 16; off > 0; off >>= 1) {
        cNC += __shfl_xor_sync(0xFFFFFFFFu, cNC, off);
        cNP += __shfl_xor_sync(0xFFFFFFFFu, cNP, off);
    }

    __shared__ float s0[8], s1[8];
    const int lane = threadIdx.x & 31;
    const int wid  = threadIdx.x >> 5;
    if (lane == 0) { s0[wid] = cNC; s1[wid] = cNP; }
    __syncthreads();

    if (wid == 0) {
        float v0 = (lane < 8) ? s0[lane] : 0.0f;
        float v1 = (lane < 8) ? s1[lane] : 0.0f;
#pragma unroll
        for (int off = 4; off > 0; off >>= 1) {
            v0 += __shfl_xor_sync(0xFFFFFFFFu, v0, off);
            v1 += __shfl_xor_sync(0xFFFFFFFFu, v1, off);
        }
        if (lane == 0) {
            atomicAdd(&g_acc[0], (double)v0);
            atomicAdd(&g_acc[1], (double)v1);
        }
    }
}

__global__ void finalize_kernel(float* __restrict__ out) {
    const double invNC = 1.0 / (double)(Bn * Cn * Hn * Wn);  // 1/16777216
    const double invNP = 1.0 / (double)(Bn * Hn * Wn);       // 1/2097152
    out[0] = (float)(g_acc[0] * invNC + g_acc[1] * invNP);
}

extern "C" void kernel_launch(void* const* d_in, const int* in_sizes, int n_in,
                              void* d_out, int out_size)
{
    const float* atts   = (const float*)d_in[0];
    const float* dets   = (const float*)d_in[1];
    const float* target = (const float*)d_in[2];
    const float* con    = (const float*)d_in[3];
    float* out = (float*)d_out;

    zero_acc_kernel<<<1, 1>>>();
    dim3 grid(Wn / 256, Hn, Bn);
    bicon_main_kernel<<<grid, 256>>>(atts, dets, target, con);
    finalize_kernel<<<1, 1>>>(out);
}

// round 4
// speedup vs baseline: 1.0854x; 1.0854x over previous
#include <cuda_runtime.h>

// Problem dims (fixed by the reference)
#define Bn 8
#define Cn 8
#define Hn 512
#define Wn 512
#define HWn (Hn * Wn)

#define TILE_W 32
#define TILE_H 16
#define HALO_W (TILE_W + 2)   // 34
#define HALO_H (TILE_H + 2)   // 18
#define NTHREADS (TILE_W * TILE_H)          // 512
#define ELEMS (HALO_W * HALO_H)             // 612
#define GRID_X (Wn / TILE_W)                // 16
#define GRID_Y (Hn / TILE_H)                // 32
#define NBLOCKS (GRID_X * GRID_Y * Bn)      // 4096

// Per-block partial sums: x = NC-normalized part, y = NP-normalized part.
__device__ float2 g_part[NBLOCKS];

__device__ __forceinline__ float ex2f(float x) {
    float r; asm("ex2.approx.f32 %0, %1;" : "=f"(r) : "f"(x)); return r;
}
__device__ __forceinline__ float lg2f(float x) {
    float r; asm("lg2.approx.f32 %0, %1;" : "=f"(r) : "f"(x)); return r;
}

__global__ __launch_bounds__(NTHREADS) void bicon_main_kernel(
    const float* __restrict__ atts,
    const float* __restrict__ dets,
    const float* __restrict__ target,
    const float* __restrict__ con)
{
    const float L2E = 1.4426950408889634f;
    const float LN2 = 0.6931471805599453f;

    // 8-neighborhood, raster order; vote channel k pairs center channel k
    // with channel (7-k) at offset (DH[k], DW[k]).  (Validated: rel_err 0.0 in R2.)
    const int DH[8] = {-1, -1, -1,  0, 0,  1, 1, 1};
    const int DW[8] = {-1,  0,  1, -1, 1, -1, 0, 1};

    // log-sigmoid tiles: [branch*8 + channel][row][col]
    __shared__ float sm[16][HALO_H][HALO_W];

    const int tx = threadIdx.x;          // 0..31
    const int ty = threadIdx.y;          // 0..15
    const int tid = ty * TILE_W + tx;    // 0..511
    const int w0 = blockIdx.x * TILE_W;
    const int h0 = blockIdx.y * TILE_H;
    const int b  = blockIdx.z;

    // ---------- Phase 1: load halo tiles, compute log-sigmoid once per element,
    // ---------- fold the conn-BCE (0.8-weighted term) in-flight.
    float connAcc = 0.0f;   // sum over interior elements of (s1 - t*x1) + (s2 - t*x2)

    for (int i = tid; i < Cn * ELEMS; i += NTHREADS) {
        const int c   = i / ELEMS;
        const int r   = i - c * ELEMS;
        const int row = r / HALO_W;
        const int col = r - row * HALO_W;
        const int gh  = h0 + row - 1;
        const int gw  = w0 + col - 1;
        const bool valid = ((unsigned)gh < (unsigned)Hn) && ((unsigned)gw < (unsigned)Wn);

        float lp1 = -1e30f, lp2 = -1e30f;
        if (valid) {
            const int gi = (b * Cn + c) * HWn + gh * Wn + gw;
            const float x1 = __ldg(atts + gi);
            const float x2 = __ldg(dets + gi);
            const float s1 = LN2 * lg2f(1.0f + ex2f(x1 * L2E));  // softplus(x1)
            const float s2 = LN2 * lg2f(1.0f + ex2f(x2 * L2E));
            lp1 = x1 - s1;   // log sigmoid(x1)
            lp2 = x2 - s2;

            // conn BCE term, counted once per (b,c,h,w): interior only
            const bool interior = (row >= 1) && (row <= TILE_H) &&
                                  (col >= 1) && (col <= TILE_W);
            if (interior) {
                const float t = __ldg(con + gi);
                connAcc += (s1 + s2) - t * (x1 + x2);
            }
        }
        sm[c][row][col]     = lp1;
        sm[c + 8][row][col] = lp2;
    }
    __syncthreads();

    // ---------- Phase 2: per-pixel combine (each thread owns one pixel).
    const int gh = h0 + ty;
    const int gw = w0 + tx;

    float csum = 0.0f;
    float bic1 = 0.0f, bic2 = 0.0f;
    float sv1 = 0.0f, sv2 = 0.0f;
    float mv2 = 1e30f;

#pragma unroll
    for (int k = 0; k < 8; k++) {
        const int rr = ty + 1 + DH[k];
        const int cc = tx + 1 + DW[k];

        const float lpx1 = sm[k][ty + 1][tx + 1];
        const float lpy1 = sm[7 - k][rr][cc];
        const float lpx2 = sm[8 + k][ty + 1][tx + 1];
        const float lpy2 = sm[8 + (7 - k)][rr][cc];

        const float t = __ldg(con + (b * Cn + k) * HWn + gh * Wn + gw);
        csum += t;
        const bool tp = (t > 0.5f);

        const float lv1 = lpx1 + lpy1;            // log v1 (natural)
        const float v1  = ex2f(lv1 * L2E);
        sv1 += v1;

        const float lv2 = lpx2 + lpy2;
        const float v2  = ex2f(lv2 * L2E);
        sv2 += v2;
        mv2 = fminf(mv2, v2);

        // BCE(v, t) with -100 clamp; log(1-v) computed like the reference (f32, from v)
        const float l1 = tp ? fmaxf(lv1, -100.0f)
                            : fmaxf(LN2 * lg2f(1.0f - v1), -100.0f);
        const float l2 = tp ? fmaxf(lv2, -100.0f)
                            : fmaxf(LN2 * lg2f(1.0f - v2), -100.0f);
        bic1 -= l1;
        bic2 -= l2;
    }

    const float tgt  = __ldg(target + b * HWn + gh * Wn + gw);
    const bool  tpos = (tgt > 0.5f);

    // glo_map BCE (atts branch)
    const float g1   = sv1 * 0.125f;
    const float bce1 = tpos ? -fmaxf(LN2 * lg2f(g1),        -100.0f)
                            : -fmaxf(LN2 * lg2f(1.0f - g1), -100.0f);

    // decouple BCE (dets branch)
    const float g2   = sv2 * 0.125f;
    const bool  edge = (csum > 0.5f) && (csum < 7.5f);
    const float dec  = edge ? (1.0f - mv2) : g2;
    const float de2  = tpos ? -fmaxf(LN2 * lg2f(dec),        -100.0f)
                            : -fmaxf(LN2 * lg2f(1.0f - dec), -100.0f);

    // Per-thread contributions; normalized in the reduce kernel:
    //   cNC / (B*C*H*W),   cNP / (B*H*W)
    float cNC = 0.2f * (bic1 + bic2) + 0.8f * connAcc;
    float cNP = bce1 + de2;

    // ---------- Block reduction (512 threads -> one float2)
#pragma unroll
    for (int off = 16; off > 0; off >>= 1) {
        cNC += __shfl_xor_sync(0xFFFFFFFFu, cNC, off);
        cNP += __shfl_xor_sync(0xFFFFFFFFu, cNP, off);
    }
    __shared__ float r0[16], r1[16];
    const int lane = tid & 31;
    const int wid  = tid >> 5;
    if (lane == 0) { r0[wid] = cNC; r1[wid] = cNP; }
    __syncthreads();
    if (wid == 0) {
        float a = (lane < 16) ? r0[lane] : 0.0f;
        float c = (lane < 16) ? r1[lane] : 0.0f;
#pragma unroll
        for (int off = 8; off > 0; off >>= 1) {
            a += __shfl_xor_sync(0xFFFFFFFFu, a, off);
            c += __shfl_xor_sync(0xFFFFFFFFu, c, off);
        }
        if (lane == 0) {
            const int bid = blockIdx.x + GRID_X * (blockIdx.y + GRID_Y * blockIdx.z);
            g_part[bid] = make_float2(a, c);
        }
    }
}

__global__ __launch_bounds__(512) void reduce_kernel(float* __restrict__ out)
{
    double a = 0.0, c = 0.0;
    for (int i = threadIdx.x; i < NBLOCKS; i += 512) {
        const float2 p = g_part[i];
        a += (double)p.x;
        c += (double)p.y;
    }
#pragma unroll
    for (int off = 16; off > 0; off >>= 1) {
        a += __shfl_xor_sync(0xFFFFFFFFu, a, off);
        c += __shfl_xor_sync(0xFFFFFFFFu, c, off);
    }
    __shared__ double s0[16], s1[16];
    const int lane = threadIdx.x & 31;
    const int wid  = threadIdx.x >> 5;
    if (lane == 0) { s0[wid] = a; s1[wid] = c; }
    __syncthreads();
    if (wid == 0) {
        double x = (lane < 16) ? s0[lane] : 0.0;
        double y = (lane < 16) ? s1[lane] : 0.0;
#pragma unroll
        for (int off = 8; off > 0; off >>= 1) {
            x += __shfl_xor_sync(0xFFFFFFFFu, x, off);
            y += __shfl_xor_sync(0xFFFFFFFFu, y, off);
        }
        if (lane == 0) {
            const double invNC = 1.0 / (double)(Bn * Cn * Hn * Wn);
            const double invNP = 1.0 / (double)(Bn * Hn * Wn);
            out[0] = (float)(x * invNC + y * invNP);
        }
    }
}

extern "C" void kernel_launch(void* const* d_in, const int* in_sizes, int n_in,
                              void* d_out, int out_size)
{
    const float* atts   = (const float*)d_in[0];
    const float* dets   = (const float*)d_in[1];
    const float* target = (const float*)d_in[2];
    const float* con    = (const float*)d_in[3];
    float* out = (float*)d_out;

    dim3 grid(GRID_X, GRID_Y, Bn);
    dim3 block(TILE_W, TILE_H);
    bicon_main_kernel<<<grid, block>>>(atts, dets, target, con);
    reduce_kernel<<<1, 512>>>(out);
}